// round 4
// baseline (speedup 1.0000x reference)
#include <cuda_runtime.h>
#include <cstdint>

// Problem constants
#define Bc  4
#define Tc  2048
#define Cc  1024
#define NHc 16
#define HDc 64

// ---------------------------------------------------------------------------
// Scratch (no cudaMalloc allowed)
// ---------------------------------------------------------------------------
__device__ float g_q[Bc * NHc * Tc * HDc];     // [B*NH, T, HD]
__device__ float g_k[Bc * NHc * Tc * HDc];
__device__ float g_v[Bc * NHc * Tc * HDc];
__device__ float g_y[Bc * Tc * Cc];            // attention out [B,T,C] (tf32-rounded)
__device__ float g_xr[Bc * Tc * Cc];           // tf32-rounded x
__device__ float g_wa_t[3 * Cc * Cc];          // W_attn^T  [3C, C] tf32-rounded
__device__ float g_wp_t[Cc * Cc];              // W_proj^T  [C, C]  tf32-rounded

__device__ __forceinline__ float tf32r(float x) {
    uint32_t r;
    asm("cvt.rna.tf32.f32 %0, %1;" : "=r"(r) : "f"(x));
    return __uint_as_float(r);
}

__device__ __forceinline__ void mma_tf32(float& d0, float& d1, float& d2, float& d3,
                                         uint32_t a0, uint32_t a1, uint32_t a2, uint32_t a3,
                                         uint32_t b0, uint32_t b1)
{
    asm volatile(
        "mma.sync.aligned.m16n8k8.row.col.f32.tf32.tf32.f32 "
        "{%0,%1,%2,%3}, {%4,%5,%6,%7}, {%8,%9}, {%0,%1,%2,%3};"
        : "+f"(d0), "+f"(d1), "+f"(d2), "+f"(d3)
        : "r"(a0), "r"(a1), "r"(a2), "r"(a3), "r"(b0), "r"(b1));
}

// ---------------------------------------------------------------------------
// tf32 mma.sync GEMM:  Out[M,N] = A[M,K] @ Bt[N,K]^T + bias
// BM=BN=128, BK=16, 256 threads (8 warps, 2x4 -> warp tile 64x32).
// Shared layout is k-paired: s[ks][row][c] = float2(X[row][k0+8ks+c], X[row][k0+8ks+c+4])
// so each mma fragment is ONE conflict-free LDS.64.
// SCATTER=1: epilogue scatters into g_q/g_k/g_v. SCATTER=0: writes Out.
// ---------------------------------------------------------------------------
constexpr int BMg = 128, BNg = 128, BKg = 16;

template <int SCATTER>
__global__ __launch_bounds__(256)
void gemm_mma(const float* __restrict__ A, const float* __restrict__ Bt,
              const float* __restrict__ bias, float* __restrict__ Out,
              int K, int N)
{
    __shared__ float2 As2[2][2][BMg][4];   // [buf][ks][row][c]  16 KB
    __shared__ float2 Bs2[2][2][BNg][4];   // 16 KB

    const int tid  = threadIdx.x;
    const int lane = tid & 31;
    const int wid  = tid >> 5;
    const int g    = lane >> 2;   // 0..7
    const int c    = lane & 3;    // 0..3
    const int warp_m = (wid & 1) * 64;
    const int warp_n = (wid >> 1) * 32;

    const int row  = tid >> 1;    // 0..127 (tile row for loads)
    const int half = tid & 1;     // k-step 0/1

    const float* Ap = A  + (size_t)(blockIdx.y * BMg + row) * K + half * 8;
    const float* Bp = Bt + (size_t)(blockIdx.x * BNg + row) * K + half * 8;

    float4 ar0, ar1, br0, br1;

    auto ldg_tile = [&](int k0) {
        ar0 = *(const float4*)(Ap + k0);
        ar1 = *(const float4*)(Ap + k0 + 4);
        br0 = *(const float4*)(Bp + k0);
        br1 = *(const float4*)(Bp + k0 + 4);
    };
    auto sts_tile = [&](int buf) {
        As2[buf][half][row][0] = make_float2(ar0.x, ar1.x);
        As2[buf][half][row][1] = make_float2(ar0.y, ar1.y);
        As2[buf][half][row][2] = make_float2(ar0.z, ar1.z);
        As2[buf][half][row][3] = make_float2(ar0.w, ar1.w);
        Bs2[buf][half][row][0] = make_float2(br0.x, br1.x);
        Bs2[buf][half][row][1] = make_float2(br0.y, br1.y);
        Bs2[buf][half][row][2] = make_float2(br0.z, br1.z);
        Bs2[buf][half][row][3] = make_float2(br0.w, br1.w);
    };

    float acc[4][4][4];
#pragma unroll
    for (int i = 0; i < 4; i++)
#pragma unroll
        for (int j = 0; j < 4; j++)
#pragma unroll
            for (int r = 0; r < 4; r++) acc[i][j][r] = 0.f;

    const int NT = K / BKg;
    ldg_tile(0);
    sts_tile(0);
    __syncthreads();

    for (int kt = 0; kt < NT; kt++) {
        const int buf = kt & 1;
        if (kt + 1 < NT) ldg_tile((kt + 1) * BKg);

#pragma unroll
        for (int ks = 0; ks < 2; ks++) {
            uint32_t af[4][4], bf[4][2];
#pragma unroll
            for (int mt = 0; mt < 4; mt++) {
                float2 x02 = As2[buf][ks][warp_m + mt * 16 + g][c];
                float2 x13 = As2[buf][ks][warp_m + mt * 16 + 8 + g][c];
                af[mt][0] = __float_as_uint(x02.x);
                af[mt][1] = __float_as_uint(x13.x);
                af[mt][2] = __float_as_uint(x02.y);
                af[mt][3] = __float_as_uint(x13.y);
            }
#pragma unroll
            for (int nt = 0; nt < 4; nt++) {
                float2 b01 = Bs2[buf][ks][warp_n + nt * 8 + g][c];
                bf[nt][0] = __float_as_uint(b01.x);
                bf[nt][1] = __float_as_uint(b01.y);
            }
#pragma unroll
            for (int mt = 0; mt < 4; mt++)
#pragma unroll
                for (int nt = 0; nt < 4; nt++)
                    mma_tf32(acc[mt][nt][0], acc[mt][nt][1], acc[mt][nt][2], acc[mt][nt][3],
                             af[mt][0], af[mt][1], af[mt][2], af[mt][3],
                             bf[nt][0], bf[nt][1]);
        }
        __syncthreads();
        if (kt + 1 < NT) {
            sts_tile(buf ^ 1);
            __syncthreads();
        }
    }

    // Epilogue: C fragment rows = lane/4 (+8), cols = 2*(lane%4)+{0,1}
#pragma unroll
    for (int mt = 0; mt < 4; mt++) {
#pragma unroll
        for (int nt = 0; nt < 4; nt++) {
            int n0 = blockIdx.x * BNg + warp_n + nt * 8 + 2 * c;
            float2 bb = *(const float2*)(bias + n0);
            int m0 = blockIdx.y * BMg + warp_m + mt * 16 + g;
#pragma unroll
            for (int rh = 0; rh < 2; rh++) {
                int m = m0 + rh * 8;
                float2 v = { acc[mt][nt][2 * rh + 0] + bb.x,
                             acc[mt][nt][2 * rh + 1] + bb.y };
                if (SCATTER) {
                    int which = n0 >> 10, c0 = n0 & 1023;
                    int h = c0 >> 6, d = c0 & 63;
                    int b = m >> 11, t = m & 2047;
                    float* dst = (which == 0) ? g_q : ((which == 1) ? g_k : g_v);
                    *(float2*)&dst[(((size_t)(b * NHc + h)) * Tc + t) * HDc + d] = v;
                } else {
                    *(float2*)&Out[(size_t)m * N + n0] = v;
                }
            }
        }
    }
}

// ---------------------------------------------------------------------------
// Prep: tf32-round x; transpose+round W into [N,K]
// ---------------------------------------------------------------------------
__global__ void round_x_kernel(const float* __restrict__ x, int n4)
{
    int i = blockIdx.x * blockDim.x + threadIdx.x;
    if (i < n4) {
        float4 v = ((const float4*)x)[i];
        v.x = tf32r(v.x); v.y = tf32r(v.y); v.z = tf32r(v.z); v.w = tf32r(v.w);
        ((float4*)g_xr)[i] = v;
    }
}

__global__ void transpose_round(const float* __restrict__ W, float* __restrict__ Bt,
                                int K, int N)
{
    __shared__ float t[32][33];
    int n0 = blockIdx.x * 32, k0 = blockIdx.y * 32;
    int tx = threadIdx.x, ty = threadIdx.y;
#pragma unroll
    for (int i = 0; i < 32; i += 8)
        t[ty + i][tx] = W[(size_t)(k0 + ty + i) * N + n0 + tx];
    __syncthreads();
#pragma unroll
    for (int i = 0; i < 32; i += 8)
        Bt[(size_t)(n0 + ty + i) * K + k0 + tx] = tf32r(t[tx][ty + i]);
}

// ---------------------------------------------------------------------------
// Flash attention (fp32, exact): one thread per query row, 64-key tiles.
// Output tf32-rounded (feeds tf32 proj GEMM).
// ---------------------------------------------------------------------------
constexpr int AROWS = 128;
constexpr int KB = 64;

__global__ __launch_bounds__(128, 2)
void attn_kernel()
{
    __shared__ float Ks[KB][HDc];
    __shared__ float Vs[KB][HDc];

    int bh = blockIdx.x;
    int t  = blockIdx.y * AROWS + threadIdx.x;

    const float* qp = g_q + ((size_t)bh * Tc + t) * HDc;
    float q[HDc];
#pragma unroll
    for (int d = 0; d < HDc; d++) q[d] = qp[d] * 0.125f;

    float o[HDc] = {};
    float mval = -1e30f, l = 0.f;

    const float* kbase = g_k + (size_t)bh * Tc * HDc;
    const float* vbase = g_v + (size_t)bh * Tc * HDc;

    int kmax = blockIdx.y * AROWS + AROWS - 1;

    for (int k0 = 0; k0 <= kmax; k0 += KB) {
        __syncthreads();
#pragma unroll
        for (int i = 0; i < 8; i++) {
            int idx = threadIdx.x + i * 128;
            ((float4*)Ks)[idx] = ((const float4*)(kbase + (size_t)k0 * HDc))[idx];
            ((float4*)Vs)[idx] = ((const float4*)(vbase + (size_t)k0 * HDc))[idx];
        }
        __syncthreads();

        int jend = min(KB, t - k0 + 1);
        for (int j = 0; j < jend; j++) {
            float s0 = 0.f, s1 = 0.f, s2 = 0.f, s3 = 0.f;
            const float4* krow = (const float4*)&Ks[j][0];
#pragma unroll
            for (int d4 = 0; d4 < 16; d4++) {
                float4 k4 = krow[d4];
                s0 += q[d4 * 4 + 0] * k4.x;
                s1 += q[d4 * 4 + 1] * k4.y;
                s2 += q[d4 * 4 + 2] * k4.z;
                s3 += q[d4 * 4 + 3] * k4.w;
            }
            float s = (s0 + s1) + (s2 + s3);

            if (s > mval) {
                float corr = __expf(mval - s);
                l *= corr;
#pragma unroll
                for (int d = 0; d < HDc; d++) o[d] *= corr;
                mval = s;
            }
            float p = __expf(s - mval);
            l += p;
            const float4* vrow = (const float4*)&Vs[j][0];
#pragma unroll
            for (int d4 = 0; d4 < 16; d4++) {
                float4 v4 = vrow[d4];
                o[d4 * 4 + 0] += p * v4.x;
                o[d4 * 4 + 1] += p * v4.y;
                o[d4 * 4 + 2] += p * v4.z;
                o[d4 * 4 + 3] += p * v4.w;
            }
        }
    }

    int b = bh / NHc;
    int h = bh - b * NHc;
    float inv_l = 1.f / l;
    float* yp = g_y + ((size_t)b * Tc + t) * Cc + h * HDc;
#pragma unroll
    for (int d = 0; d < HDc; d++) yp[d] = tf32r(o[d] * inv_l);
}

// ---------------------------------------------------------------------------
// Launch
// ---------------------------------------------------------------------------
extern "C" void kernel_launch(void* const* d_in, const int* in_sizes, int n_in,
                              void* d_out, int out_size)
{
    const float* x      = (const float*)d_in[0];
    const float* W_attn = (const float*)d_in[1];
    const float* b_attn = (const float*)d_in[2];
    const float* W_proj = (const float*)d_in[3];
    const float* b_proj = (const float*)d_in[4];
    float* out = (float*)d_out;

    float *xr, *yy, *wa_t, *wp_t;
    cudaGetSymbolAddress((void**)&xr,   g_xr);
    cudaGetSymbolAddress((void**)&yy,   g_y);
    cudaGetSymbolAddress((void**)&wa_t, g_wa_t);
    cudaGetSymbolAddress((void**)&wp_t, g_wp_t);

    // Prep: round x to tf32; transpose+round weights to [N,K]
    {
        int n4 = Bc * Tc * Cc / 4;
        round_x_kernel<<<(n4 + 255) / 256, 256>>>(x, n4);
        transpose_round<<<dim3(3 * Cc / 32, Cc / 32), dim3(32, 8)>>>(W_attn, wa_t, Cc, 3 * Cc);
        transpose_round<<<dim3(Cc / 32, Cc / 32), dim3(32, 8)>>>(W_proj, wp_t, Cc, Cc);
    }

    // 1) QKV GEMM (tf32 mma.sync): [8192,1024]@[1024,3072] -> scatter g_q/g_k/g_v
    {
        dim3 grid(3 * Cc / BNg, Bc * Tc / BMg);
        gemm_mma<1><<<grid, 256>>>(xr, wa_t, b_attn, nullptr, Cc, 3 * Cc);
    }
    // 2) causal flash attention (fp32) -> g_y
    {
        dim3 grid(Bc * NHc, Tc / AROWS);
        attn_kernel<<<grid, 128>>>();
    }
    // 3) projection GEMM (tf32 mma.sync): g_y @ W_proj -> out
    {
        dim3 grid(Cc / BNg, Bc * Tc / BMg);
        gemm_mma<0><<<grid, 256>>>(yy, wp_t, b_proj, out, Cc, Cc);
    }
}

// round 7
// speedup vs baseline: 3.3316x; 3.3316x over previous
#include <cuda_runtime.h>
#include <cstdint>

// Problem constants
#define Bc  4
#define Tc  2048
#define Cc  1024
#define NHc 16
#define HDc 64

// ---------------------------------------------------------------------------
// Scratch (no cudaMalloc allowed)
// ---------------------------------------------------------------------------
__device__ float g_q[Bc * NHc * Tc * HDc];     // [B*NH, T, HD] tf32-rounded
__device__ float g_k[Bc * NHc * Tc * HDc];     // tf32-rounded
__device__ float g_v[Bc * NHc * Tc * HDc];     // tf32-rounded
__device__ float g_y[Bc * Tc * Cc];            // attention out [B,T,C] (tf32-rounded)
__device__ float g_xr[Bc * Tc * Cc];           // tf32-rounded x
__device__ float g_wa_t[3 * Cc * Cc];          // W_attn^T  [3C, C] tf32-rounded
__device__ float g_wp_t[Cc * Cc];              // W_proj^T  [C, C]  tf32-rounded

__device__ __forceinline__ float tf32r(float x) {
    uint32_t r;
    asm("cvt.rna.tf32.f32 %0, %1;" : "=r"(r) : "f"(x));
    return __uint_as_float(r);
}
__device__ __forceinline__ uint32_t smem_u32(const void* p) {
    uint32_t a;
    asm("{ .reg .u64 t; cvta.to.shared.u64 t, %1; cvt.u32.u64 %0, t; }" : "=r"(a) : "l"(p));
    return a;
}
__device__ __forceinline__ void cp16(uint32_t dst, const void* src) {
    asm volatile("cp.async.cg.shared.global [%0], [%1], 16;" :: "r"(dst), "l"(src));
}
__device__ __forceinline__ void cp_commit() {
    asm volatile("cp.async.commit_group;" ::: "memory");
}
template <int N>
__device__ __forceinline__ void cp_wait() {
    asm volatile("cp.async.wait_group %0;" :: "n"(N) : "memory");
}

__device__ __forceinline__ void mma_tf32(float& d0, float& d1, float& d2, float& d3,
                                         uint32_t a0, uint32_t a1, uint32_t a2, uint32_t a3,
                                         uint32_t b0, uint32_t b1)
{
    asm volatile(
        "mma.sync.aligned.m16n8k8.row.col.f32.tf32.tf32.f32 "
        "{%0,%1,%2,%3}, {%4,%5,%6,%7}, {%8,%9}, {%0,%1,%2,%3};"
        : "+f"(d0), "+f"(d1), "+f"(d2), "+f"(d3)
        : "r"(a0), "r"(a1), "r"(a2), "r"(a3), "r"(b0), "r"(b1));
}

// ---------------------------------------------------------------------------
// tf32 mma.sync GEMM:  Out[M,N] = A[M,K] @ Bt[N,K]^T + bias
// (unchanged from R4 except: SCATTER epilogue tf32-rounds q/k/v so the
//  attention kernel needs no cvt in its inner loops)
// ---------------------------------------------------------------------------
constexpr int BMg = 128, BNg = 128, BKg = 16;

template <int SCATTER>
__global__ __launch_bounds__(256)
void gemm_mma(const float* __restrict__ A, const float* __restrict__ Bt,
              const float* __restrict__ bias, float* __restrict__ Out,
              int K, int N)
{
    __shared__ float2 As2[2][2][BMg][4];
    __shared__ float2 Bs2[2][2][BNg][4];

    const int tid  = threadIdx.x;
    const int lane = tid & 31;
    const int wid  = tid >> 5;
    const int g    = lane >> 2;
    const int c    = lane & 3;
    const int warp_m = (wid & 1) * 64;
    const int warp_n = (wid >> 1) * 32;

    const int row  = tid >> 1;
    const int half = tid & 1;

    const float* Ap = A  + (size_t)(blockIdx.y * BMg + row) * K + half * 8;
    const float* Bp = Bt + (size_t)(blockIdx.x * BNg + row) * K + half * 8;

    float4 ar0, ar1, br0, br1;

    auto ldg_tile = [&](int k0) {
        ar0 = *(const float4*)(Ap + k0);
        ar1 = *(const float4*)(Ap + k0 + 4);
        br0 = *(const float4*)(Bp + k0);
        br1 = *(const float4*)(Bp + k0 + 4);
    };
    auto sts_tile = [&](int buf) {
        As2[buf][half][row][0] = make_float2(ar0.x, ar1.x);
        As2[buf][half][row][1] = make_float2(ar0.y, ar1.y);
        As2[buf][half][row][2] = make_float2(ar0.z, ar1.z);
        As2[buf][half][row][3] = make_float2(ar0.w, ar1.w);
        Bs2[buf][half][row][0] = make_float2(br0.x, br1.x);
        Bs2[buf][half][row][1] = make_float2(br0.y, br1.y);
        Bs2[buf][half][row][2] = make_float2(br0.z, br1.z);
        Bs2[buf][half][row][3] = make_float2(br0.w, br1.w);
    };

    float acc[4][4][4];
#pragma unroll
    for (int i = 0; i < 4; i++)
#pragma unroll
        for (int j = 0; j < 4; j++)
#pragma unroll
            for (int r = 0; r < 4; r++) acc[i][j][r] = 0.f;

    const int NT = K / BKg;
    ldg_tile(0);
    sts_tile(0);
    __syncthreads();

    for (int kt = 0; kt < NT; kt++) {
        const int buf = kt & 1;
        if (kt + 1 < NT) ldg_tile((kt + 1) * BKg);

#pragma unroll
        for (int ks = 0; ks < 2; ks++) {
            uint32_t af[4][4], bf[4][2];
#pragma unroll
            for (int mt = 0; mt < 4; mt++) {
                float2 x02 = As2[buf][ks][warp_m + mt * 16 + g][c];
                float2 x13 = As2[buf][ks][warp_m + mt * 16 + 8 + g][c];
                af[mt][0] = __float_as_uint(x02.x);
                af[mt][1] = __float_as_uint(x13.x);
                af[mt][2] = __float_as_uint(x02.y);
                af[mt][3] = __float_as_uint(x13.y);
            }
#pragma unroll
            for (int nt = 0; nt < 4; nt++) {
                float2 b01 = Bs2[buf][ks][warp_n + nt * 8 + g][c];
                bf[nt][0] = __float_as_uint(b01.x);
                bf[nt][1] = __float_as_uint(b01.y);
            }
#pragma unroll
            for (int mt = 0; mt < 4; mt++)
#pragma unroll
                for (int nt = 0; nt < 4; nt++)
                    mma_tf32(acc[mt][nt][0], acc[mt][nt][1], acc[mt][nt][2], acc[mt][nt][3],
                             af[mt][0], af[mt][1], af[mt][2], af[mt][3],
                             bf[nt][0], bf[nt][1]);
        }
        __syncthreads();
        if (kt + 1 < NT) {
            sts_tile(buf ^ 1);
            __syncthreads();
        }
    }

#pragma unroll
    for (int mt = 0; mt < 4; mt++) {
#pragma unroll
        for (int nt = 0; nt < 4; nt++) {
            int n0 = blockIdx.x * BNg + warp_n + nt * 8 + 2 * c;
            float2 bb = *(const float2*)(bias + n0);
            int m0 = blockIdx.y * BMg + warp_m + mt * 16 + g;
#pragma unroll
            for (int rh = 0; rh < 2; rh++) {
                int m = m0 + rh * 8;
                float2 v = { acc[mt][nt][2 * rh + 0] + bb.x,
                             acc[mt][nt][2 * rh + 1] + bb.y };
                if (SCATTER) {
                    v.x = tf32r(v.x); v.y = tf32r(v.y);   // pre-round for tf32 attention
                    int which = n0 >> 10, c0 = n0 & 1023;
                    int h = c0 >> 6, d = c0 & 63;
                    int b = m >> 11, t = m & 2047;
                    float* dst = (which == 0) ? g_q : ((which == 1) ? g_k : g_v);
                    *(float2*)&dst[(((size_t)(b * NHc + h)) * Tc + t) * HDc + d] = v;
                } else {
                    *(float2*)&Out[(size_t)m * N + n0] = v;
                }
            }
        }
    }
}

// ---------------------------------------------------------------------------
// Prep kernels
// ---------------------------------------------------------------------------
__global__ void round_x_kernel(const float* __restrict__ x, int n4)
{
    int i = blockIdx.x * blockDim.x + threadIdx.x;
    if (i < n4) {
        float4 v = ((const float4*)x)[i];
        v.x = tf32r(v.x); v.y = tf32r(v.y); v.z = tf32r(v.z); v.w = tf32r(v.w);
        ((float4*)g_xr)[i] = v;
    }
}

__global__ void transpose_round(const float* __restrict__ W, float* __restrict__ Bt,
                                int K, int N)
{
    __shared__ float t[32][33];
    int n0 = blockIdx.x * 32, k0 = blockIdx.y * 32;
    int tx = threadIdx.x, ty = threadIdx.y;
#pragma unroll
    for (int i = 0; i < 32; i += 8)
        t[ty + i][tx] = W[(size_t)(k0 + ty + i) * N + n0 + tx];
    __syncthreads();
#pragma unroll
    for (int i = 0; i < 32; i += 8)
        Bt[(size_t)(n0 + ty + i) * K + k0 + tx] = tf32r(t[tx][ty + i]);
}

// ---------------------------------------------------------------------------
// FA2 attention with mma.sync tf32.
// Block: one (bh, 128-q-row tile). 8 warps x 16 q-rows. 64-key KV tiles,
// double-buffered cp.async, stride-68 smem rows (conflict-free B-frag LDS).
// S accum -> softmax (quad shfl) -> P A-frags via register shuffle -> P@V.
// ---------------------------------------------------------------------------
constexpr int QTile = 128;
constexpr int KTile = 64;
constexpr int KVS   = 68;                       // floats per smem row (64+4 pad)
constexpr int ATTN_SMEM = 2 * 2 * KTile * KVS * 4;   // 69632 B

__global__ __launch_bounds__(256, 1)
void attn_mma()
{
    extern __shared__ float sm[];
    float* KsBase = sm;                              // [2][64][68]
    float* VsBase = sm + 2 * KTile * KVS;            // [2][64][68]

    const int qt  = (gridDim.x - 1) - blockIdx.x;    // heavy tiles first
    const int bh  = blockIdx.y;
    const int qb  = qt * QTile;
    const int tid = threadIdx.x;
    const int lane = tid & 31;
    const int w   = tid >> 5;
    const int g   = lane >> 2;
    const int c   = lane & 3;

    const float* gq = g_q + (size_t)bh * Tc * HDc;
    const float* gk = g_k + (size_t)bh * Tc * HDc;
    const float* gv = g_v + (size_t)bh * Tc * HDc;

    const int r0 = qb + w * 16 + g;                  // my two q rows: r0, r0+8

    // Q A-fragments (values pre-tf32-rounded; 0.125 scale is exact in tf32)
    uint32_t aq[8][4];
#pragma unroll
    for (int kk = 0; kk < 8; kk++) {
        aq[kk][0] = __float_as_uint(gq[(size_t)r0 * HDc + kk * 8 + c] * 0.125f);
        aq[kk][1] = __float_as_uint(gq[(size_t)(r0 + 8) * HDc + kk * 8 + c] * 0.125f);
        aq[kk][2] = __float_as_uint(gq[(size_t)r0 * HDc + kk * 8 + c + 4] * 0.125f);
        aq[kk][3] = __float_as_uint(gq[(size_t)(r0 + 8) * HDc + kk * 8 + c + 4] * 0.125f);
    }

    float o[8][4];
#pragma unroll
    for (int nt = 0; nt < 8; nt++)
#pragma unroll
        for (int j = 0; j < 4; j++) o[nt][j] = 0.f;
    float m0 = -1e30f, m1 = -1e30f, l0 = 0.f, l1 = 0.f;

    auto load_kv = [&](int t, int buf) {
        const float* ksrc = gk + (size_t)t * KTile * HDc;
        const float* vsrc = gv + (size_t)t * KTile * HDc;
        float* kd = KsBase + buf * KTile * KVS;
        float* vd = VsBase + buf * KTile * KVS;
#pragma unroll
        for (int i = 0; i < 4; i++) {
            int id = tid + i * 256;          // 0..1023
            int row = id >> 4, col = (id & 15) * 4;
            cp16(smem_u32(kd + row * KVS + col), ksrc + row * HDc + col);
            cp16(smem_u32(vd + row * KVS + col), vsrc + row * HDc + col);
        }
    };

    const int NT = 2 * (qt + 1);
    load_kv(0, 0); cp_commit();

    for (int t = 0; t < NT; t++) {
        const int buf = t & 1;
        if (t + 1 < NT) { load_kv(t + 1, buf ^ 1); cp_commit(); cp_wait<1>(); }
        else            { cp_wait<0>(); }
        __syncthreads();

        const float* KsT = KsBase + buf * KTile * KVS;
        const float* VsT = VsBase + buf * KTile * KVS;
        const int kb = t * KTile;

        // ---- S = Q @ K^T ----
        float s[8][4];
#pragma unroll
        for (int nt = 0; nt < 8; nt++)
#pragma unroll
            for (int j = 0; j < 4; j++) s[nt][j] = 0.f;

#pragma unroll
        for (int kk = 0; kk < 8; kk++) {
#pragma unroll
            for (int nt = 0; nt < 8; nt++) {
                uint32_t b0 = __float_as_uint(KsT[(nt * 8 + g) * KVS + kk * 8 + c]);
                uint32_t b1 = __float_as_uint(KsT[(nt * 8 + g) * KVS + kk * 8 + c + 4]);
                mma_tf32(s[nt][0], s[nt][1], s[nt][2], s[nt][3],
                         aq[kk][0], aq[kk][1], aq[kk][2], aq[kk][3], b0, b1);
            }
        }

        // ---- causal mask (only tiles crossing this warp's diagonal) ----
        if (kb + KTile - 1 > qb + w * 16) {
#pragma unroll
            for (int nt = 0; nt < 8; nt++) {
                int key0 = kb + nt * 8 + 2 * c;
                if (key0     > r0)     s[nt][0] = -1e30f;
                if (key0 + 1 > r0)     s[nt][1] = -1e30f;
                if (key0     > r0 + 8) s[nt][2] = -1e30f;
                if (key0 + 1 > r0 + 8) s[nt][3] = -1e30f;
            }
        }

        // ---- online softmax ----
        float rm0 = -1e30f, rm1 = -1e30f;
#pragma unroll
        for (int nt = 0; nt < 8; nt++) {
            rm0 = fmaxf(rm0, fmaxf(s[nt][0], s[nt][1]));
            rm1 = fmaxf(rm1, fmaxf(s[nt][2], s[nt][3]));
        }
        rm0 = fmaxf(rm0, __shfl_xor_sync(0xffffffffu, rm0, 1));
        rm0 = fmaxf(rm0, __shfl_xor_sync(0xffffffffu, rm0, 2));
        rm1 = fmaxf(rm1, __shfl_xor_sync(0xffffffffu, rm1, 1));
        rm1 = fmaxf(rm1, __shfl_xor_sync(0xffffffffu, rm1, 2));

        float mn0 = fmaxf(m0, rm0), mn1 = fmaxf(m1, rm1);
        float corr0 = __expf(m0 - mn0), corr1 = __expf(m1 - mn1);
        m0 = mn0; m1 = mn1;

        float ls0 = 0.f, ls1 = 0.f;
        uint32_t pu[8][4];
#pragma unroll
        for (int nt = 0; nt < 8; nt++) {
            float p0 = __expf(s[nt][0] - m0);
            float p1 = __expf(s[nt][1] - m0);
            float p2 = __expf(s[nt][2] - m1);
            float p3 = __expf(s[nt][3] - m1);
            ls0 += p0 + p1;  ls1 += p2 + p3;
            pu[nt][0] = __float_as_uint(tf32r(p0));
            pu[nt][1] = __float_as_uint(tf32r(p1));
            pu[nt][2] = __float_as_uint(tf32r(p2));
            pu[nt][3] = __float_as_uint(tf32r(p3));
        }
        ls0 += __shfl_xor_sync(0xffffffffu, ls0, 1);
        ls0 += __shfl_xor_sync(0xffffffffu, ls0, 2);
        ls1 += __shfl_xor_sync(0xffffffffu, ls1, 1);
        ls1 += __shfl_xor_sync(0xffffffffu, ls1, 2);
        l0 = l0 * corr0 + ls0;
        l1 = l1 * corr1 + ls1;
#pragma unroll
        for (int nt = 0; nt < 8; nt++) {
            o[nt][0] *= corr0; o[nt][1] *= corr0;
            o[nt][2] *= corr1; o[nt][3] *= corr1;
        }

        // ---- O += P @ V  (P A-frags via register shuffle) ----
        const int src0 = g * 4 + (c >> 1);
        const int src1 = src0 + 2;
        const bool odd = (c & 1);
#pragma unroll
        for (int kk = 0; kk < 8; kk++) {
            uint32_t e0 = __shfl_sync(0xffffffffu, pu[kk][0], src0);
            uint32_t q0 = __shfl_sync(0xffffffffu, pu[kk][1], src0);
            uint32_t e1 = __shfl_sync(0xffffffffu, pu[kk][2], src0);
            uint32_t q1 = __shfl_sync(0xffffffffu, pu[kk][3], src0);
            uint32_t e2 = __shfl_sync(0xffffffffu, pu[kk][0], src1);
            uint32_t q2 = __shfl_sync(0xffffffffu, pu[kk][1], src1);
            uint32_t e3 = __shfl_sync(0xffffffffu, pu[kk][2], src1);
            uint32_t q3 = __shfl_sync(0xffffffffu, pu[kk][3], src1);
            uint32_t a0 = odd ? q0 : e0;
            uint32_t a1 = odd ? q1 : e1;
            uint32_t a2 = odd ? q2 : e2;
            uint32_t a3 = odd ? q3 : e3;
#pragma unroll
            for (int nt = 0; nt < 8; nt++) {
                uint32_t b0 = __float_as_uint(VsT[(kk * 8 + c) * KVS + nt * 8 + g]);
                uint32_t b1 = __float_as_uint(VsT[(kk * 8 + c + 4) * KVS + nt * 8 + g]);
                mma_tf32(o[nt][0], o[nt][1], o[nt][2], o[nt][3],
                         a0, a1, a2, a3, b0, b1);
            }
        }
        __syncthreads();
    }

    // ---- write O / l to g_y (tf32-rounded for proj GEMM) ----
    float inv0 = 1.f / l0, inv1 = 1.f / l1;
    int b = bh >> 4, h = bh & 15;
    float* y0 = g_y + ((size_t)b * Tc + r0) * Cc + h * HDc;
    float* y1 = y0 + (size_t)8 * Cc;
#pragma unroll
    for (int nt = 0; nt < 8; nt++) {
        float2 v0 = { tf32r(o[nt][0] * inv0), tf32r(o[nt][1] * inv0) };
        float2 v1 = { tf32r(o[nt][2] * inv1), tf32r(o[nt][3] * inv1) };
        *(float2*)&y0[nt * 8 + 2 * c] = v0;
        *(float2*)&y1[nt * 8 + 2 * c] = v1;
    }
}

// ---------------------------------------------------------------------------
// Launch
// ---------------------------------------------------------------------------
extern "C" void kernel_launch(void* const* d_in, const int* in_sizes, int n_in,
                              void* d_out, int out_size)
{
    const float* x      = (const float*)d_in[0];
    const float* W_attn = (const float*)d_in[1];
    const float* b_attn = (const float*)d_in[2];
    const float* W_proj = (const float*)d_in[3];
    const float* b_proj = (const float*)d_in[4];
    float* out = (float*)d_out;

    float *xr, *yy, *wa_t, *wp_t;
    cudaGetSymbolAddress((void**)&xr,   g_xr);
    cudaGetSymbolAddress((void**)&yy,   g_y);
    cudaGetSymbolAddress((void**)&wa_t, g_wa_t);
    cudaGetSymbolAddress((void**)&wp_t, g_wp_t);

    cudaFuncSetAttribute(attn_mma, cudaFuncAttributeMaxDynamicSharedMemorySize, ATTN_SMEM);

    // Prep
    {
        int n4 = Bc * Tc * Cc / 4;
        round_x_kernel<<<(n4 + 255) / 256, 256>>>(x, n4);
        transpose_round<<<dim3(3 * Cc / 32, Cc / 32), dim3(32, 8)>>>(W_attn, wa_t, Cc, 3 * Cc);
        transpose_round<<<dim3(Cc / 32, Cc / 32), dim3(32, 8)>>>(W_proj, wp_t, Cc, Cc);
    }
    // 1) QKV GEMM -> scatter tf32 q/k/v
    {
        dim3 grid(3 * Cc / BNg, Bc * Tc / BMg);
        gemm_mma<1><<<grid, 256>>>(xr, wa_t, b_attn, nullptr, Cc, 3 * Cc);
    }
    // 2) FA2 tensor-core attention -> g_y
    {
        dim3 grid(Tc / QTile, Bc * NHc);
        attn_mma<<<grid, 256, ATTN_SMEM>>>();
    }
    // 3) projection GEMM -> out
    {
        dim3 grid(Cc / BNg, Bc * Tc / BMg);
        gemm_mma<0><<<grid, 256>>>(yy, wp_t, b_proj, out, Cc, Cc);
    }
}

// round 9
// speedup vs baseline: 6.2509x; 1.8762x over previous
#include <cuda_runtime.h>
#include <cuda_fp16.h>
#include <cstdint>

// Problem constants
#define Bc  4
#define Tc  2048
#define Cc  1024
#define NHc 16
#define HDc 64

// ---------------------------------------------------------------------------
// Scratch (no cudaMalloc allowed) — all fp16 now
// ---------------------------------------------------------------------------
__device__ __half g_qh[Bc * NHc * Tc * HDc];   // [B*NH, T, HD]
__device__ __half g_kh[Bc * NHc * Tc * HDc];
__device__ __half g_vh[Bc * NHc * Tc * HDc];
__device__ __half g_yh[Bc * Tc * Cc];          // attention out [B,T,C]
__device__ __half g_xh[Bc * Tc * Cc];          // fp16 x
__device__ __half g_wa_th[3 * Cc * Cc];        // W_attn^T [3C, C]
__device__ __half g_wp_th[Cc * Cc];            // W_proj^T [C, C]

__device__ __forceinline__ uint32_t smem_u32(const void* p) {
    uint32_t a;
    asm("{ .reg .u64 t; cvta.to.shared.u64 t, %1; cvt.u32.u64 %0, t; }" : "=r"(a) : "l"(p));
    return a;
}
__device__ __forceinline__ void cp16(uint32_t dst, const void* src) {
    asm volatile("cp.async.cg.shared.global [%0], [%1], 16;" :: "r"(dst), "l"(src));
}
__device__ __forceinline__ void cp_commit() {
    asm volatile("cp.async.commit_group;" ::: "memory");
}
template <int N>
__device__ __forceinline__ void cp_wait() {
    asm volatile("cp.async.wait_group %0;" :: "n"(N) : "memory");
}
__device__ __forceinline__ uint32_t h2u(__half2 h) { return *reinterpret_cast<uint32_t*>(&h); }

__device__ __forceinline__ void mma_f16(float& d0, float& d1, float& d2, float& d3,
                                        uint32_t a0, uint32_t a1, uint32_t a2, uint32_t a3,
                                        uint32_t b0, uint32_t b1)
{
    asm volatile(
        "mma.sync.aligned.m16n8k16.row.col.f32.f16.f16.f32 "
        "{%0,%1,%2,%3}, {%4,%5,%6,%7}, {%8,%9}, {%0,%1,%2,%3};"
        : "+f"(d0), "+f"(d1), "+f"(d2), "+f"(d3)
        : "r"(a0), "r"(a1), "r"(a2), "r"(a3), "r"(b0), "r"(b1));
}
__device__ __forceinline__ void ldm_x4(uint32_t& r0, uint32_t& r1, uint32_t& r2, uint32_t& r3,
                                       uint32_t addr)
{
    asm volatile("ldmatrix.sync.aligned.m8n8.x4.shared.b16 {%0,%1,%2,%3}, [%4];"
                 : "=r"(r0), "=r"(r1), "=r"(r2), "=r"(r3) : "r"(addr));
}
__device__ __forceinline__ void ldm_x4_t(uint32_t& r0, uint32_t& r1, uint32_t& r2, uint32_t& r3,
                                         uint32_t addr)
{
    asm volatile("ldmatrix.sync.aligned.m8n8.x4.trans.shared.b16 {%0,%1,%2,%3}, [%4];"
                 : "=r"(r0), "=r"(r1), "=r"(r2), "=r"(r3) : "r"(addr));
}

// ---------------------------------------------------------------------------
// fp16 mma GEMM: Out[M,N] = A[M,K]@Bt[N,K]^T + bias. BM=BN=128, BK=32,
// 256 threads, 8 warps (64x32 warp tiles). k-paired smem: uint2 = (pair c, pair c+4)
// per k16 step -> single LDS.64 per fragment pair.
// SCATTER=1: half epilogue into g_qh/g_kh/g_vh; SCATTER=0: fp32 Out.
// ---------------------------------------------------------------------------
constexpr int BMg = 128, BNg = 128;

template <int SCATTER>
__global__ __launch_bounds__(256)
void gemm_h(const __half* __restrict__ A, const __half* __restrict__ Bt,
            const float* __restrict__ bias, float* __restrict__ Out,
            int K, int N)
{
    __shared__ uint2 As2[2][2][BMg][4];   // [buf][ks][row][c]  16 KB
    __shared__ uint2 Bs2[2][2][BNg][4];   // 16 KB

    const int tid  = threadIdx.x;
    const int lane = tid & 31;
    const int wid  = tid >> 5;
    const int g    = lane >> 2;
    const int c    = lane & 3;
    const int warp_m = (wid & 1) * 64;
    const int warp_n = (wid >> 1) * 32;

    const int row  = tid >> 1;
    const int half = tid & 1;

    const __half* Ap = A  + (size_t)(blockIdx.y * BMg + row) * K + half * 16;
    const __half* Bp = Bt + (size_t)(blockIdx.x * BNg + row) * K + half * 16;

    uint4 au, av, bu, bv;
    auto ldg_tile = [&](int k0) {
        au = *(const uint4*)(Ap + k0);      // pairs 0..3 of this ks
        av = *(const uint4*)(Ap + k0 + 8);  // pairs 4..7
        bu = *(const uint4*)(Bp + k0);
        bv = *(const uint4*)(Bp + k0 + 8);
    };
    auto sts_tile = [&](int buf) {
        As2[buf][half][row][0] = make_uint2(au.x, av.x);
        As2[buf][half][row][1] = make_uint2(au.y, av.y);
        As2[buf][half][row][2] = make_uint2(au.z, av.z);
        As2[buf][half][row][3] = make_uint2(au.w, av.w);
        Bs2[buf][half][row][0] = make_uint2(bu.x, bv.x);
        Bs2[buf][half][row][1] = make_uint2(bu.y, bv.y);
        Bs2[buf][half][row][2] = make_uint2(bu.z, bv.z);
        Bs2[buf][half][row][3] = make_uint2(bu.w, bv.w);
    };

    float acc[4][4][4];
#pragma unroll
    for (int i = 0; i < 4; i++)
#pragma unroll
        for (int j = 0; j < 4; j++)
#pragma unroll
            for (int r = 0; r < 4; r++) acc[i][j][r] = 0.f;

    const int NT = K / 32;
    ldg_tile(0);
    sts_tile(0);
    __syncthreads();

    for (int kt = 0; kt < NT; kt++) {
        const int buf = kt & 1;
        if (kt + 1 < NT) ldg_tile((kt + 1) * 32);

#pragma unroll
        for (int ks = 0; ks < 2; ks++) {
            uint32_t af[4][4], bf[4][2];
#pragma unroll
            for (int mt = 0; mt < 4; mt++) {
                uint2 lo = As2[buf][ks][warp_m + mt * 16 + g][c];
                uint2 hi = As2[buf][ks][warp_m + mt * 16 + 8 + g][c];
                af[mt][0] = lo.x;  af[mt][1] = hi.x;
                af[mt][2] = lo.y;  af[mt][3] = hi.y;
            }
#pragma unroll
            for (int nt = 0; nt < 4; nt++) {
                uint2 bb = Bs2[buf][ks][warp_n + nt * 8 + g][c];
                bf[nt][0] = bb.x;  bf[nt][1] = bb.y;
            }
#pragma unroll
            for (int mt = 0; mt < 4; mt++)
#pragma unroll
                for (int nt = 0; nt < 4; nt++)
                    mma_f16(acc[mt][nt][0], acc[mt][nt][1], acc[mt][nt][2], acc[mt][nt][3],
                            af[mt][0], af[mt][1], af[mt][2], af[mt][3],
                            bf[nt][0], bf[nt][1]);
        }
        __syncthreads();
        if (kt + 1 < NT) {
            sts_tile(buf ^ 1);
            __syncthreads();
        }
    }

#pragma unroll
    for (int mt = 0; mt < 4; mt++) {
#pragma unroll
        for (int nt = 0; nt < 4; nt++) {
            int n0 = blockIdx.x * BNg + warp_n + nt * 8 + 2 * c;
            float2 bb = *(const float2*)(bias + n0);
            int m0 = blockIdx.y * BMg + warp_m + mt * 16 + g;
#pragma unroll
            for (int rh = 0; rh < 2; rh++) {
                int m = m0 + rh * 8;
                float vx = acc[mt][nt][2 * rh + 0] + bb.x;
                float vy = acc[mt][nt][2 * rh + 1] + bb.y;
                if (SCATTER) {
                    __half2 hv = __float22half2_rn(make_float2(vx, vy));
                    int which = n0 >> 10, c0 = n0 & 1023;
                    int h = c0 >> 6, d = c0 & 63;
                    int b = m >> 11, t = m & 2047;
                    __half* dst = (which == 0) ? g_qh : ((which == 1) ? g_kh : g_vh);
                    *(__half2*)&dst[(((size_t)(b * NHc + h)) * Tc + t) * HDc + d] = hv;
                } else {
                    *(float2*)&Out[(size_t)m * N + n0] = make_float2(vx, vy);
                }
            }
        }
    }
}

// ---------------------------------------------------------------------------
// Prep kernels: fp32 -> fp16
// ---------------------------------------------------------------------------
__global__ void conv_x_kernel(const float* __restrict__ x, int n4)
{
    int i = blockIdx.x * blockDim.x + threadIdx.x;
    if (i < n4) {
        float4 v = ((const float4*)x)[i];
        __half2 h0 = __float22half2_rn(make_float2(v.x, v.y));
        __half2 h1 = __float22half2_rn(make_float2(v.z, v.w));
        ((__half2*)g_xh)[2 * i]     = h0;
        ((__half2*)g_xh)[2 * i + 1] = h1;
    }
}

__global__ void transpose_conv(const float* __restrict__ W, __half* __restrict__ Bt,
                               int K, int N)
{
    __shared__ float t[32][33];
    int n0 = blockIdx.x * 32, k0 = blockIdx.y * 32;
    int tx = threadIdx.x, ty = threadIdx.y;
#pragma unroll
    for (int i = 0; i < 32; i += 8)
        t[ty + i][tx] = W[(size_t)(k0 + ty + i) * N + n0 + tx];
    __syncthreads();
#pragma unroll
    for (int i = 0; i < 32; i += 8)
        Bt[(size_t)(n0 + ty + i) * K + k0 + tx] = __float2half_rn(t[tx][ty + i]);
}

// ---------------------------------------------------------------------------
// FA2 attention, fp16 mma m16n8k16.
// Block: (bh, 128-q tile). 8 warps x 16 q-rows. 64-key KV tiles, double-buffered
// cp.async, stride-72-half rows (144B, 16B-aligned, conflict-free ldmatrix).
// K frags: ldmatrix; V frags: ldmatrix.trans; P frags: lane-local pack (no shfl).
// ---------------------------------------------------------------------------
constexpr int QTile = 128;
constexpr int KTile = 64;
constexpr int KVSH  = 72;                                // halves per smem row
constexpr int ATTN_SMEM = 2 * 2 * KTile * KVSH * 2;      // 36864 B

__global__ __launch_bounds__(256)
void attn_h()
{
    extern __shared__ __half smh[];
    __half* KsBase = smh;                          // [2][64][72]
    __half* VsBase = smh + 2 * KTile * KVSH;       // [2][64][72]

    const int qt  = (gridDim.x - 1) - blockIdx.x;  // heavy tiles first
    const int bh  = blockIdx.y;
    const int qb  = qt * QTile;
    const int tid = threadIdx.x;
    const int lane = tid & 31;
    const int w   = tid >> 5;
    const int g   = lane >> 2;
    const int c   = lane & 3;

    const __half* gq = g_qh + (size_t)bh * Tc * HDc;
    const __half* gk = g_kh + (size_t)bh * Tc * HDc;
    const __half* gv = g_vh + (size_t)bh * Tc * HDc;

    const int r0 = qb + w * 16 + g;                // rows r0, r0+8

    // Q fragments, pre-scaled by 1/sqrt(HD)=0.125 (exact exponent shift)
    const __half2 scl = __float2half2_rn(0.125f);
    const __half2* q0p = (const __half2*)(gq + (size_t)r0 * HDc);
    const __half2* q1p = (const __half2*)(gq + (size_t)(r0 + 8) * HDc);
    uint32_t aq[4][4];
#pragma unroll
    for (int kk = 0; kk < 4; kk++) {
        aq[kk][0] = h2u(__hmul2(q0p[8 * kk + c],     scl));
        aq[kk][1] = h2u(__hmul2(q1p[8 * kk + c],     scl));
        aq[kk][2] = h2u(__hmul2(q0p[8 * kk + c + 4], scl));
        aq[kk][3] = h2u(__hmul2(q1p[8 * kk + c + 4], scl));
    }

    float o[8][4];
#pragma unroll
    for (int nt = 0; nt < 8; nt++)
#pragma unroll
        for (int j = 0; j < 4; j++) o[nt][j] = 0.f;
    float m0 = -1e30f, m1 = -1e30f, l0 = 0.f, l1 = 0.f;

    auto load_kv = [&](int t, int buf) {
        const __half* ksrc = gk + (size_t)t * KTile * HDc;
        const __half* vsrc = gv + (size_t)t * KTile * HDc;
        __half* kd = KsBase + buf * KTile * KVSH;
        __half* vd = VsBase + buf * KTile * KVSH;
#pragma unroll
        for (int i = 0; i < 2; i++) {
            int id = tid + i * 256;                // 0..511
            int row = id >> 3, ch = (id & 7) * 8;  // chunk of 8 halves (16B)
            cp16(smem_u32(kd + row * KVSH + ch), ksrc + row * HDc + ch);
            cp16(smem_u32(vd + row * KVSH + ch), vsrc + row * HDc + ch);
        }
    };

    const int NT = 2 * (qt + 1);
    load_kv(0, 0); cp_commit();

    for (int t = 0; t < NT; t++) {
        const int buf = t & 1;
        if (t + 1 < NT) { load_kv(t + 1, buf ^ 1); cp_commit(); cp_wait<1>(); }
        else            { cp_wait<0>(); }
        __syncthreads();

        const uint32_t ksb = smem_u32(KsBase + buf * KTile * KVSH);
        const uint32_t vsb = smem_u32(VsBase + buf * KTile * KVSH);
        const int kb = t * KTile;

        // ---- S = Q @ K^T ----
        float s[8][4];
#pragma unroll
        for (int nt = 0; nt < 8; nt++)
#pragma unroll
            for (int j = 0; j < 4; j++) s[nt][j] = 0.f;

#pragma unroll
        for (int nt = 0; nt < 8; nt++) {
            uint32_t k0r, k1r, k2r, k3r;
            // x4 #1: keys nt*8+(l&7), hd (l>>3)*8 -> kk0 b0,b1 / kk1 b0,b1
            uint32_t addr = ksb + (uint32_t)(((nt * 8 + (lane & 7)) * KVSH + (lane >> 3) * 8) * 2);
            ldm_x4(k0r, k1r, k2r, k3r, addr);
            mma_f16(s[nt][0], s[nt][1], s[nt][2], s[nt][3],
                    aq[0][0], aq[0][1], aq[0][2], aq[0][3], k0r, k1r);
            mma_f16(s[nt][0], s[nt][1], s[nt][2], s[nt][3],
                    aq[1][0], aq[1][1], aq[1][2], aq[1][3], k2r, k3r);
            // x4 #2: hd +32 halves (64 B)
            ldm_x4(k0r, k1r, k2r, k3r, addr + 64);
            mma_f16(s[nt][0], s[nt][1], s[nt][2], s[nt][3],
                    aq[2][0], aq[2][1], aq[2][2], aq[2][3], k0r, k1r);
            mma_f16(s[nt][0], s[nt][1], s[nt][2], s[nt][3],
                    aq[3][0], aq[3][1], aq[3][2], aq[3][3], k2r, k3r);
        }

        // ---- causal mask ----
        if (kb + KTile - 1 > qb + w * 16) {
#pragma unroll
            for (int nt = 0; nt < 8; nt++) {
                int key0 = kb + nt * 8 + 2 * c;
                if (key0     > r0)     s[nt][0] = -1e30f;
                if (key0 + 1 > r0)     s[nt][1] = -1e30f;
                if (key0     > r0 + 8) s[nt][2] = -1e30f;
                if (key0 + 1 > r0 + 8) s[nt][3] = -1e30f;
            }
        }

        // ---- online softmax ----
        float rm0 = -1e30f, rm1 = -1e30f;
#pragma unroll
        for (int nt = 0; nt < 8; nt++) {
            rm0 = fmaxf(rm0, fmaxf(s[nt][0], s[nt][1]));
            rm1 = fmaxf(rm1, fmaxf(s[nt][2], s[nt][3]));
        }
        rm0 = fmaxf(rm0, __shfl_xor_sync(0xffffffffu, rm0, 1));
        rm0 = fmaxf(rm0, __shfl_xor_sync(0xffffffffu, rm0, 2));
        rm1 = fmaxf(rm1, __shfl_xor_sync(0xffffffffu, rm1, 1));
        rm1 = fmaxf(rm1, __shfl_xor_sync(0xffffffffu, rm1, 2));

        float mn0 = fmaxf(m0, rm0), mn1 = fmaxf(m1, rm1);
        float corr0 = __expf(m0 - mn0), corr1 = __expf(m1 - mn1);
        m0 = mn0; m1 = mn1;

        float ls0 = 0.f, ls1 = 0.f;
        uint32_t pu0[8], pu1[8];   // pu0: row r0 (P[2c],P[2c+1]); pu1: row r0+8
#pragma unroll
        for (int nt = 0; nt < 8; nt++) {
            float p0 = __expf(s[nt][0] - m0);
            float p1 = __expf(s[nt][1] - m0);
            float p2 = __expf(s[nt][2] - m1);
            float p3 = __expf(s[nt][3] - m1);
            ls0 += p0 + p1;  ls1 += p2 + p3;
            pu0[nt] = h2u(__float22half2_rn(make_float2(p0, p1)));
            pu1[nt] = h2u(__float22half2_rn(make_float2(p2, p3)));
        }
        ls0 += __shfl_xor_sync(0xffffffffu, ls0, 1);
        ls0 += __shfl_xor_sync(0xffffffffu, ls0, 2);
        ls1 += __shfl_xor_sync(0xffffffffu, ls1, 1);
        ls1 += __shfl_xor_sync(0xffffffffu, ls1, 2);
        l0 = l0 * corr0 + ls0;
        l1 = l1 * corr1 + ls1;
#pragma unroll
        for (int nt = 0; nt < 8; nt++) {
            o[nt][0] *= corr0; o[nt][1] *= corr0;
            o[nt][2] *= corr1; o[nt][3] *= corr1;
        }

        // ---- O += P @ V  (P A-frags are lane-local; V via ldmatrix.trans) ----
#pragma unroll
        for (int kk2 = 0; kk2 < 4; kk2++) {
            uint32_t a0 = pu0[2 * kk2],     a1 = pu1[2 * kk2];
            uint32_t a2 = pu0[2 * kk2 + 1], a3 = pu1[2 * kk2 + 1];
#pragma unroll
            for (int ntp = 0; ntp < 4; ntp++) {
                uint32_t v0, v1, v2, v3;
                uint32_t addr = vsb + (uint32_t)((
                    (kk2 * 16 + ((lane >> 3) & 1) * 8 + (lane & 7)) * KVSH +
                    (2 * ntp + (lane >> 4)) * 8) * 2);
                ldm_x4_t(v0, v1, v2, v3, addr);
                mma_f16(o[2 * ntp][0], o[2 * ntp][1], o[2 * ntp][2], o[2 * ntp][3],
                        a0, a1, a2, a3, v0, v1);
                mma_f16(o[2 * ntp + 1][0], o[2 * ntp + 1][1], o[2 * ntp + 1][2], o[2 * ntp + 1][3],
                        a0, a1, a2, a3, v2, v3);
            }
        }
        __syncthreads();
    }

    // ---- write O / l to g_yh ----
    float inv0 = 1.f / l0, inv1 = 1.f / l1;
    int b = bh >> 4, h = bh & 15;
    __half* y0 = g_yh + ((size_t)b * Tc + r0) * Cc + h * HDc;
    __half* y1 = y0 + (size_t)8 * Cc;
#pragma unroll
    for (int nt = 0; nt < 8; nt++) {
        *(__half2*)&y0[nt * 8 + 2 * c] =
            __float22half2_rn(make_float2(o[nt][0] * inv0, o[nt][1] * inv0));
        *(__half2*)&y1[nt * 8 + 2 * c] =
            __float22half2_rn(make_float2(o[nt][2] * inv1, o[nt][3] * inv1));
    }
}

// ---------------------------------------------------------------------------
// Launch
// ---------------------------------------------------------------------------
extern "C" void kernel_launch(void* const* d_in, const int* in_sizes, int n_in,
                              void* d_out, int out_size)
{
    const float* x      = (const float*)d_in[0];
    const float* W_attn = (const float*)d_in[1];
    const float* b_attn = (const float*)d_in[2];
    const float* W_proj = (const float*)d_in[3];
    const float* b_proj = (const float*)d_in[4];
    float* out = (float*)d_out;

    __half *xh, *yh, *wa_t, *wp_t;
    cudaGetSymbolAddress((void**)&xh,   g_xh);
    cudaGetSymbolAddress((void**)&yh,   g_yh);
    cudaGetSymbolAddress((void**)&wa_t, g_wa_th);
    cudaGetSymbolAddress((void**)&wp_t, g_wp_th);

    // Prep: fp32 -> fp16
    {
        int n4 = Bc * Tc * Cc / 4;
        conv_x_kernel<<<(n4 + 255) / 256, 256>>>(x, n4);
        transpose_conv<<<dim3(3 * Cc / 32, Cc / 32), dim3(32, 8)>>>(W_attn, wa_t, Cc, 3 * Cc);
        transpose_conv<<<dim3(Cc / 32, Cc / 32), dim3(32, 8)>>>(W_proj, wp_t, Cc, Cc);
    }
    // 1) QKV GEMM (fp16) -> scatter g_qh/g_kh/g_vh
    {
        dim3 grid(3 * Cc / BNg, Bc * Tc / BMg);
        gemm_h<1><<<grid, 256>>>(xh, wa_t, b_attn, nullptr, Cc, 3 * Cc);
    }
    // 2) FA2 fp16 tensor-core attention -> g_yh
    {
        dim3 grid(Tc / QTile, Bc * NHc);
        attn_h<<<grid, 256, ATTN_SMEM>>>();
    }
    // 3) projection GEMM (fp16) -> out (fp32)
    {
        dim3 grid(Cc / BNg, Bc * Tc / BMg);
        gemm_h<0><<<grid, 256>>>(yh, wp_t, b_proj, out, Cc, Cc);
    }
}